// round 13
// baseline (speedup 1.0000x reference)
#include <cuda_runtime.h>
#include <math.h>

#define GRID 128
#define NT 512

// ---------------- scratch ----------------
__device__ __align__(16) float g_Ppart[64 * 32 * 1024]; // [chunk(64)][o][d]  (L2-resident)
__device__ __align__(16) float g_MTp[8 * 16 * 1024];    // [oct(8)][n][d]
__device__ __align__(16) float g_Pp[1024 * 32];         // [k][o] plain
__device__ __align__(16) float g_MT[16 * 1024];         // [n][d]
__device__ float g_c[32];
__device__ float g_k1[32];
__device__ float g_k2[32];
__device__ __align__(16) float g_au[2 * 32 * 4096];     // [b][o][s]
__device__ __align__(16) float g_states[2 * 16 * 4096]; // [b*16+n][s]
__device__ int g_cnt;                                   // barrier (monotonic)

typedef unsigned long long ull;
__device__ __forceinline__ ull dup_f(float v) {
    ull r; asm("mov.b64 %0, {%1, %1};" : "=l"(r) : "f"(v)); return r;
}
__device__ __forceinline__ ull pack2(float a, float b) {
    ull r; asm("mov.b64 %0, {%1, %2};" : "=l"(r) : "f"(a), "f"(b)); return r;
}
#define FFMA2(acc, a, b) asm("fma.rn.f32x2 %0, %1, %2, %0;" : "+l"(acc) : "l"(a), "l"(b))
#define ADD2(acc, a)     asm("add.rn.f32x2 %0, %0, %1;" : "+l"(acc) : "l"(a))
__device__ __forceinline__ void unpk(float& lo, float& hi, ull v) {
    asm("mov.b64 {%0, %1}, %2;" : "=f"(lo), "=f"(hi) : "l"(v));
}

// grid-wide barrier: monotonic counter, replay-safe
__device__ __forceinline__ void gsync() {
    __syncthreads();
    if (threadIdx.x == 0) {
        __threadfence();
        int arrival = atomicAdd(&g_cnt, 1);
        int target = (arrival / GRID + 1) * GRID;
        while (*((volatile int*)&g_cnt) < target) { }
        __threadfence();
    }
    __syncthreads();
}

// ---------------- single fused kernel ----------------
__global__ void __launch_bounds__(NT) k_main(const float* __restrict__ x,
                                             const float* __restrict__ nw,
                                             const float* __restrict__ nb,
                                             const float* __restrict__ Win,
                                             const float* __restrict__ b_in,
                                             const float* __restrict__ A,
                                             const float* __restrict__ Bs,
                                             const float* __restrict__ C,
                                             const float* __restrict__ Wout,
                                             const float* __restrict__ bo,
                                             float* __restrict__ out) {
    extern __shared__ float dsm[];   // 16896 floats = 67584 B
    __shared__ float sMu[64], sRs[64];
    int tid = threadIdx.x;
    int blk = blockIdx.x;
    int lane = tid & 31, wid = tid >> 5;

    // ================= Phase A: P split-K partials, ALL 256 units =================
    {
        ull* sAB2 = (ull*)dsm + (tid >> 8) * 1024;  // 8KB per unit
        int t2 = tid & 255;
        int unit = blk * 2 + (tid >> 8);
        int dt = unit >> 6;          // 0..3  (d-tile of 256)
        int chunk = unit & 63;       // 0..63 (e-chunk of 32)
        int e0 = chunk * 32;
        for (int i = t2; i < 512; i += 256) {
            int el = i >> 4, n = i & 15;
            sAB2[el * 32 + n]      = dup_f(A [(e0 + el) * 16 + n]);
            sAB2[el * 32 + 16 + n] = dup_f(Bs[(e0 + el) * 16 + n]);
        }
        __syncthreads();
        int dp = t2 >> 1, oh = t2 & 1;
        int d = dt * 256 + dp * 2;
        ull acc[16];
#pragma unroll
        for (int o = 0; o < 16; o++) acc[o] = 0ull;
#pragma unroll
        for (int b8 = 0; b8 < 4; b8++) {
            ull w[8];
#pragma unroll
            for (int i = 0; i < 8; i++)
                w[i] = *(const ull*)(Win + (e0 + b8 * 8 + i) * 1024 + d);
#pragma unroll
            for (int i = 0; i < 8; i++) {
                const ull* base = sAB2 + (b8 * 8 + i) * 32 + oh * 16;
#pragma unroll
                for (int o = 0; o < 16; o++) FFMA2(acc[o], w[i], base[o]);
            }
        }
#pragma unroll
        for (int o = 0; o < 16; o++)
            *(ull*)(g_Ppart + (chunk * 32 + oh * 16 + o) * 1024 + d) = acc[o];
    }
    gsync();

    // ================= Phase B: fold-P (0-31) | bias (32) | MT partials (33-96) =================
    if (blk < 32) {
        __shared__ float sred[32];
        int o = blk;
        float s1 = 0.f, s2 = 0.f;
#pragma unroll
        for (int h = 0; h < 2; h++) {
            int d = tid + h * 512;
            float p = 0.f;
#pragma unroll 16
            for (int c = 0; c < 64; c++) p += g_Ppart[(c * 32 + o) * 1024 + d];
            float pp = nw[d] * p;
            s1 += pp;
            s2 += nb[d] * p;
            g_Pp[d * 32 + o] = pp;
        }
#pragma unroll
        for (int off = 16; off; off >>= 1) {
            s1 += __shfl_down_sync(0xffffffffu, s1, off);
            s2 += __shfl_down_sync(0xffffffffu, s2, off);
        }
        if (lane == 0) { sred[wid] = s1; sred[16 + wid] = s2; }
        __syncthreads();
        if (tid == 0) {
            float S1 = 0.f, S2 = 0.f;
#pragma unroll
            for (int j = 0; j < 16; j++) { S1 += sred[j]; S2 += sred[16 + j]; }
            g_k1[blk] = S1;
            g_k2[blk] = S2;
        }
    } else if (blk == 32) {
        float* red = dsm + (tid >> 8) * 128;
        int t2 = tid & 255;
        int half = tid >> 8;
        int l2 = t2 & 31, w2 = t2 >> 5;
        const float* G = half ? Bs : A;
        float acc[16];
#pragma unroll
        for (int n = 0; n < 16; n++) acc[n] = 0.f;
        for (int e = t2; e < 2048; e += 256) {
            float bv = b_in[e];
            const float4* g4 = (const float4*)(G + e * 16);
            float4 c0 = g4[0], c1 = g4[1], c2 = g4[2], c3 = g4[3];
            acc[0] += bv * c0.x; acc[1] += bv * c0.y; acc[2] += bv * c0.z; acc[3] += bv * c0.w;
            acc[4] += bv * c1.x; acc[5] += bv * c1.y; acc[6] += bv * c1.z; acc[7] += bv * c1.w;
            acc[8] += bv * c2.x; acc[9] += bv * c2.y; acc[10]+= bv * c2.z; acc[11]+= bv * c2.w;
            acc[12]+= bv * c3.x; acc[13]+= bv * c3.y; acc[14]+= bv * c3.z; acc[15]+= bv * c3.w;
        }
#pragma unroll
        for (int off = 16; off; off >>= 1)
#pragma unroll
            for (int n = 0; n < 16; n++) acc[n] += __shfl_down_sync(0xffffffffu, acc[n], off);
        if (l2 == 0) {
#pragma unroll
            for (int n = 0; n < 16; n++) red[w2 * 16 + n] = acc[n];
        }
        __syncthreads();
        if (t2 < 16) {
            float s = 0.f;
#pragma unroll
            for (int j = 0; j < 8; j++) s += red[j * 16 + t2];
            g_c[half * 16 + t2] = s;
        }
    } else if (blk <= 96) {
        float* sC = dsm + (tid >> 8) * 2048;
        int t2 = tid & 255;
        int unit = (blk - 33) * 2 + (tid >> 8);
        int tile = unit >> 3;
        int oct = unit & 7;
        int row = tile * 64 + (t2 >> 2);
        int nq = t2 & 3;
        ull acc0 = 0ull, acc1 = 0ull;
        for (int c = 0; c < 2; c++) {
            int e0 = oct * 256 + c * 128;
            __syncthreads();
            for (int i = t2; i < 512; i += 256)
                ((float4*)sC)[i] = ((const float4*)(C + e0 * 16))[i];
            __syncthreads();
            const float* wrow = Wout + row * 2048 + e0;
#pragma unroll 8
            for (int g = 0; g < 32; g++) {
                float4 w4 = *(const float4*)(wrow + g * 4);
#pragma unroll
                for (int j = 0; j < 4; j++) {
                    float wv = (j == 0) ? w4.x : (j == 1) ? w4.y : (j == 2) ? w4.z : w4.w;
                    ull wd = dup_f(wv);
                    ulonglong2 cp = *(const ulonglong2*)(sC + (g * 4 + j) * 16 + nq * 4);
                    FFMA2(acc0, wd, cp.x);
                    FFMA2(acc1, wd, cp.y);
                }
            }
        }
        float a[4];
        unpk(a[0], a[1], acc0);
        unpk(a[2], a[3], acc1);
#pragma unroll
        for (int i = 0; i < 4; i++) {
            int n = nq * 4 + i;
            g_MTp[(oct * 16 + n) * 1024 + row] = a[i];
        }
    }
    gsync();

    // ================= Phase C: LN + projection, 8tok x 4out tiles, pair-packed ===========
    {
        float* sXT = dsm;          // 2 x (64 k x 68) = 8704 floats
        float* sPD = dsm + 8704;   // 2 x (64 k x 64 dup) = 8192 floats
        int T0 = blk * 64;
        int w = wid;
        int ow = w & 1, ks = w >> 1;      // warp-uniform
        int tg8 = lane & 7, ol = lane >> 3;
        int o0 = ow * 16 + ol * 4;

        ull s1p[4] = {0,0,0,0}, s2p[4] = {0,0,0,0};

        // prologue: chunk 0
        {
            int prow = tid >> 3, pcol = tid & 7;
            float4 pv = *(const float4*)(g_Pp + prow * 32 + pcol * 4);
            float* pd = sPD + prow * 64 + pcol * 8;
            *(float4*)pd       = make_float4(pv.x, pv.x, pv.y, pv.y);
            *(float4*)(pd + 4) = make_float4(pv.z, pv.z, pv.w, pv.w);
#pragma unroll
            for (int it = 0; it < 2; it++) {
                int slot = tid + it * 512;
                int k = slot & 63, tq = slot >> 6;
                const float* src = x + (T0 + tq * 4) * 1024 + k;
                float a0 = src[0], a1 = src[1024], a2 = src[2048], a3 = src[3072];
                *(float4*)&sXT[k * 68 + tq * 4] = make_float4(a0, a1, a2, a3);
                ull p01 = pack2(a0, a1), p23 = pack2(a2, a3);
                ADD2(s1p[it * 2], p01); ADD2(s1p[it * 2 + 1], p23);
                FFMA2(s2p[it * 2], p01, p01); FFMA2(s2p[it * 2 + 1], p23, p23);
            }
            __syncthreads();
        }

        ull acc[16];
#pragma unroll
        for (int i = 0; i < 16; i++) acc[i] = 0ull;

        for (int c = 0; c < 16; c++) {
            int buf = c & 1;
            float xa[2][4];
            float4 pv;
            if (c < 15) {
                int prow = tid >> 3, pcol = tid & 7;
                pv = *(const float4*)(g_Pp + ((c + 1) * 64 + prow) * 32 + pcol * 4);
#pragma unroll
                for (int it = 0; it < 2; it++) {
                    int slot = tid + it * 512;
                    int k = slot & 63, tq = slot >> 6;
                    const float* src = x + (T0 + tq * 4) * 1024 + (c + 1) * 64 + k;
                    xa[it][0] = src[0]; xa[it][1] = src[1024];
                    xa[it][2] = src[2048]; xa[it][3] = src[3072];
                }
            }
            const float* xb = sXT + buf * 4352 + tg8 * 8;
            const float* pb = sPD + buf * 4096 + o0 * 2;
#pragma unroll
            for (int kl = 0; kl < 8; kl++) {
                int k = ks * 8 + kl;
                ulonglong2 xp0 = *(const ulonglong2*)(xb + k * 68);
                ulonglong2 xp1 = *(const ulonglong2*)(xb + k * 68 + 4);
                ulonglong2 pd0 = *(const ulonglong2*)(pb + k * 64);
                ulonglong2 pd1 = *(const ulonglong2*)(pb + k * 64 + 4);
                FFMA2(acc[0],  xp0.x, pd0.x); FFMA2(acc[1],  xp0.x, pd0.y);
                FFMA2(acc[2],  xp0.x, pd1.x); FFMA2(acc[3],  xp0.x, pd1.y);
                FFMA2(acc[4],  xp0.y, pd0.x); FFMA2(acc[5],  xp0.y, pd0.y);
                FFMA2(acc[6],  xp0.y, pd1.x); FFMA2(acc[7],  xp0.y, pd1.y);
                FFMA2(acc[8],  xp1.x, pd0.x); FFMA2(acc[9],  xp1.x, pd0.y);
                FFMA2(acc[10], xp1.x, pd1.x); FFMA2(acc[11], xp1.x, pd1.y);
                FFMA2(acc[12], xp1.y, pd0.x); FFMA2(acc[13], xp1.y, pd0.y);
                FFMA2(acc[14], xp1.y, pd1.x); FFMA2(acc[15], xp1.y, pd1.y);
            }
            if (c < 15) {
                int prow = tid >> 3, pcol = tid & 7;
                float* pd = sPD + (buf ^ 1) * 4096 + prow * 64 + pcol * 8;
                *(float4*)pd       = make_float4(pv.x, pv.x, pv.y, pv.y);
                *(float4*)(pd + 4) = make_float4(pv.z, pv.z, pv.w, pv.w);
#pragma unroll
                for (int it = 0; it < 2; it++) {
                    int slot = tid + it * 512;
                    int k = slot & 63, tq = slot >> 6;
                    *(float4*)&sXT[(buf ^ 1) * 4352 + k * 68 + tq * 4] =
                        make_float4(xa[it][0], xa[it][1], xa[it][2], xa[it][3]);
                    ull p01 = pack2(xa[it][0], xa[it][1]), p23 = pack2(xa[it][2], xa[it][3]);
                    ADD2(s1p[it * 2], p01); ADD2(s1p[it * 2 + 1], p23);
                    FFMA2(s2p[it * 2], p01, p01); FFMA2(s2p[it * 2 + 1], p23, p23);
                }
            }
            __syncthreads();
        }

        // ---- stats reduction (dsm reused; tiles dead) ----
        {
            ull* sp = (ull*)&dsm[tid * 16];
            sp[0] = s1p[0]; sp[1] = s1p[1]; sp[2] = s2p[0]; sp[3] = s2p[1];
            sp[4] = s1p[2]; sp[5] = s1p[3]; sp[6] = s2p[2]; sp[7] = s2p[3];
        }
        __syncthreads();
        if (tid < 64) {
            int q = tid >> 2, j = tid & 3;
            int base = (q & 7) * 64;
            int off1 = (q < 8) ? j : 8 + j;
            int off2 = off1 + 4;
            float S1 = 0.f, S2 = 0.f;
            for (int kk = 0; kk < 64; kk++) {
                S1 += dsm[(base + kk) * 16 + off1];
                S2 += dsm[(base + kk) * 16 + off2];
            }
            float mu = S1 * (1.f / 1024.f);
            float var = S2 * (1.f / 1024.f) - mu * mu;
            sMu[tid] = mu;
            sRs[tid] = rsqrtf(var + 1e-5f);
        }
        __syncthreads();

        // ---- k-split combine ----
        if (ks > 0) {
            ull* d8 = (ull*)&dsm[((ks - 1) * 64 + ow * 32 + lane) * 32];
#pragma unroll
            for (int i = 0; i < 16; i++) d8[i] = acc[i];
        }
        __syncthreads();
        if (ks == 0) {
#pragma unroll
            for (int s = 1; s < 8; s++) {
                const ull* src = (const ull*)&dsm[((s - 1) * 64 + ow * 32 + lane) * 32];
#pragma unroll
                for (int i = 0; i < 16; i++) ADD2(acc[i], src[i]);
            }
            int b = T0 >> 12;
            int s0 = (T0 & 4095) + tg8 * 8;
            float mu[8], rs[8];
#pragma unroll
            for (int j = 0; j < 8; j++) { mu[j] = sMu[tg8 * 8 + j]; rs[j] = sRs[tg8 * 8 + j]; }
#pragma unroll
            for (int oi = 0; oi < 4; oi++) {
                int o = o0 + oi;
                float k1v = g_k1[o];
                float k2v = g_k2[o] + g_c[o];
                float v[8];
#pragma unroll
                for (int p = 0; p < 4; p++) unpk(v[2 * p], v[2 * p + 1], acc[p * 4 + oi]);
#pragma unroll
                for (int j = 0; j < 8; j++) {
                    float val = rs[j] * v[j] - mu[j] * rs[j] * k1v + k2v;
                    if (o < 16) val = 1.f / (1.f + __expf(-val));
                    v[j] = val;
                }
                float* dst = g_au + (b * 32 + o) * 4096 + s0;
                *(float4*)dst       = make_float4(v[0], v[1], v[2], v[3]);
                *(float4*)(dst + 4) = make_float4(v[4], v[5], v[6], v[7]);
            }
        }
    }
    gsync();

    // ================= Phase D: scan (0-31) | fold-MT (32-63) =================
    if (blk < 32) {
        __shared__ float wA[16], wU[16], pU[16];
        int bn = blk;
        int b = bn >> 4, n = bn & 15;
        const float* ap = g_au + (b * 32 + n) * 4096;
        const float* up = g_au + (b * 32 + 16 + n) * 4096;

        float a[8], u[8];
        const float4* a4 = (const float4*)(ap + tid * 8);
        const float4* u4 = (const float4*)(up + tid * 8);
#pragma unroll
        for (int q = 0; q < 2; q++) {
            float4 av = a4[q], uv = u4[q];
            a[q*4+0] = av.x; a[q*4+1] = av.y; a[q*4+2] = av.z; a[q*4+3] = av.w;
            u[q*4+0] = uv.x; u[q*4+1] = uv.y; u[q*4+2] = uv.z; u[q*4+3] = uv.w;
        }
        float Aloc = 1.f, Uloc = 0.f;
#pragma unroll
        for (int i = 0; i < 8; i++) { Uloc = Uloc * a[i] + u[i]; Aloc *= a[i]; }

        float Ai = Aloc, Ui = Uloc;
#pragma unroll
        for (int off = 1; off < 32; off <<= 1) {
            float Ap = __shfl_up_sync(0xffffffffu, Ai, off);
            float Up = __shfl_up_sync(0xffffffffu, Ui, off);
            if (lane >= off) { Ui = Up * Ai + Ui; Ai = Ap * Ai; }
        }
        if (lane == 31) { wA[wid] = Ai; wU[wid] = Ui; }
        __syncthreads();
        if (tid == 0) {
            float Uc = 0.f;
#pragma unroll
            for (int j = 0; j < 16; j++) {
                pU[j] = Uc;
                Uc = Uc * wA[j] + wU[j];
            }
        }
        __syncthreads();
        float eA = __shfl_up_sync(0xffffffffu, Ai, 1);
        float eU = __shfl_up_sync(0xffffffffu, Ui, 1);
        if (lane == 0) { eA = 1.f; eU = 0.f; }
        float s = pU[wid] * eA + eU;

        float o8[8];
#pragma unroll
        for (int i = 0; i < 8; i++) { s = a[i] * s + u[i]; o8[i] = s; }
        float4* dst = (float4*)(g_states + bn * 4096 + tid * 8);
#pragma unroll
        for (int q = 0; q < 2; q++)
            dst[q] = make_float4(o8[q*4+0], o8[q*4+1], o8[q*4+2], o8[q*4+3]);
    } else if (blk < 64) {
        int base = (blk - 32) * 512 + tid;
        int d = base & 1023, n = base >> 10;
        float s = 0.f;
#pragma unroll
        for (int q = 0; q < 8; q++) s += g_MTp[(q * 16 + n) * 1024 + d];
        g_MT[n * 1024 + d] = s;
    }
    gsync();

    // ================= Phase E: out =================
    {
        float* sST = dsm;   // 64 tokens x 17
        int T0 = blk * 64;
        int b = T0 >> 12, s0 = T0 & 4095;
#pragma unroll
        for (int it = 0; it < 2; it++) {
            int idx = tid + it * 512;
            int soff = idx & 63, n = idx >> 6;
            sST[soff * 17 + n] = g_states[(b * 16 + n) * 4096 + s0 + soff];
        }
        int dq = tid & 255;
        int th = tid >> 8;
        ull m01[16], m23[16];
#pragma unroll
        for (int n = 0; n < 16; n++) {
            ulonglong2 mm = *(const ulonglong2*)(g_MT + n * 1024 + dq * 4);
            m01[n] = mm.x; m23[n] = mm.y;
        }
        ulonglong2 bov = *(const ulonglong2*)(bo + dq * 4);
        __syncthreads();

        for (int tl = 0; tl < 32; tl++) {
            int t = th * 32 + tl;
            ulonglong2 xv = *(const ulonglong2*)(x + (T0 + t) * 1024 + dq * 4);
            ull r01, r23;
            asm("add.rn.f32x2 %0, %1, %2;" : "=l"(r01) : "l"(xv.x), "l"(bov.x));
            asm("add.rn.f32x2 %0, %1, %2;" : "=l"(r23) : "l"(xv.y), "l"(bov.y));
#pragma unroll
            for (int n = 0; n < 16; n++) {
                ull sv = dup_f(sST[t * 17 + n]);
                FFMA2(r01, sv, m01[n]);
                FFMA2(r23, sv, m23[n]);
            }
            ulonglong2 res; res.x = r01; res.y = r23;
            *(ulonglong2*)(out + (T0 + t) * 1024 + dq * 4) = res;
        }
    }
}

// ---------------- launch ----------------
extern "C" void kernel_launch(void* const* d_in, const int* in_sizes, int n_in,
                              void* d_out, int out_size) {
    const float* x    = (const float*)d_in[0];
    const float* nw   = (const float*)d_in[1];
    const float* nb   = (const float*)d_in[2];
    const float* Win  = (const float*)d_in[3];
    const float* b_in = (const float*)d_in[4];
    const float* A    = (const float*)d_in[5];
    const float* Bs   = (const float*)d_in[6];
    const float* C    = (const float*)d_in[7];
    const float* Wout = (const float*)d_in[8];
    const float* bo   = (const float*)d_in[9];
    float* out = (float*)d_out;

    cudaFuncSetAttribute(k_main, cudaFuncAttributeMaxDynamicSharedMemorySize, 69632);

    k_main<<<GRID, NT, 67584>>>(x, nw, nb, Win, b_in, A, Bs, C, Wout, bo, out);
}

// round 14
// speedup vs baseline: 1.2281x; 1.2281x over previous
#include <cuda_runtime.h>
#include <math.h>

#define GRID 128
#define NT 512

// ---------------- scratch ----------------
__device__ __align__(16) float g_Ppart[64 * 32 * 1024]; // [chunk(64)][o][d]  (L2-resident)
__device__ __align__(16) float g_MTp[8 * 16 * 1024];    // [oct(8)][n][d]
__device__ __align__(16) float g_Pp[1024 * 32];         // [k][o] plain
__device__ __align__(16) float g_MT[16 * 1024];         // [n][d]
__device__ float g_c[32];
__device__ float g_k1[32];
__device__ float g_k2[32];
__device__ __align__(16) float g_au[2 * 32 * 4096];     // [b][o][s]
__device__ __align__(16) float g_states[2 * 16 * 4096]; // [b*16+n][s]
__device__ int g_cnt;                                   // barrier (monotonic)

typedef unsigned long long ull;
__device__ __forceinline__ ull dup_f(float v) {
    ull r; asm("mov.b64 %0, {%1, %1};" : "=l"(r) : "f"(v)); return r;
}
#define FFMA2(acc, a, b) asm("fma.rn.f32x2 %0, %1, %2, %0;" : "+l"(acc) : "l"(a), "l"(b))
#define ADD2(acc, a)     asm("add.rn.f32x2 %0, %0, %1;" : "+l"(acc) : "l"(a))
__device__ __forceinline__ void unpk(float& lo, float& hi, ull v) {
    asm("mov.b64 {%0, %1}, %2;" : "=f"(lo), "=f"(hi) : "l"(v));
}
__device__ __forceinline__ void cp16(unsigned int dst, const void* src) {
    asm volatile("cp.async.ca.shared.global [%0], [%1], 16;" :: "r"(dst), "l"(src));
}

// grid-wide barrier: monotonic counter, replay-safe
__device__ __forceinline__ void gsync() {
    __syncthreads();
    if (threadIdx.x == 0) {
        __threadfence();
        int arrival = atomicAdd(&g_cnt, 1);
        int target = (arrival / GRID + 1) * GRID;
        while (*((volatile int*)&g_cnt) < target) { }
        __threadfence();
    }
    __syncthreads();
}

// ---------------- single fused kernel ----------------
__global__ void __launch_bounds__(NT) k_main(const float* __restrict__ x,
                                             const float* __restrict__ nw,
                                             const float* __restrict__ nb,
                                             const float* __restrict__ Win,
                                             const float* __restrict__ b_in,
                                             const float* __restrict__ A,
                                             const float* __restrict__ Bs,
                                             const float* __restrict__ C,
                                             const float* __restrict__ Wout,
                                             const float* __restrict__ bo,
                                             float* __restrict__ out) {
    extern __shared__ float dsm[];   // 16896 floats = 67584 B
    int tid = threadIdx.x;
    int blk = blockIdx.x;
    int lane = tid & 31, wid = tid >> 5;

    // ================= Phase A: P split-K partials, ALL 256 units, 8-deep Win prefetch ====
    {
        ull* sAB2 = (ull*)dsm + (tid >> 8) * 1024;  // 8KB per unit
        int t2 = tid & 255;
        int unit = blk * 2 + (tid >> 8);
        int dt = unit >> 6;          // 0..3  (d-tile of 256)
        int chunk = unit & 63;       // 0..63 (e-chunk of 32)
        int e0 = chunk * 32;
        for (int i = t2; i < 512; i += 256) {
            int el = i >> 4, n = i & 15;
            sAB2[el * 32 + n]      = dup_f(A [(e0 + el) * 16 + n]);
            sAB2[el * 32 + 16 + n] = dup_f(Bs[(e0 + el) * 16 + n]);
        }
        __syncthreads();
        int dp = t2 >> 1, oh = t2 & 1;
        int d = dt * 256 + dp * 2;
        ull acc[16];
#pragma unroll
        for (int o = 0; o < 16; o++) acc[o] = 0ull;
#pragma unroll
        for (int b8 = 0; b8 < 4; b8++) {
            ull w[8];
#pragma unroll
            for (int i = 0; i < 8; i++)
                w[i] = *(const ull*)(Win + (e0 + b8 * 8 + i) * 1024 + d);
#pragma unroll
            for (int i = 0; i < 8; i++) {
                const ull* base = sAB2 + (b8 * 8 + i) * 32 + oh * 16;
#pragma unroll
                for (int o = 0; o < 16; o++) FFMA2(acc[o], w[i], base[o]);
            }
        }
#pragma unroll
        for (int o = 0; o < 16; o++)
            *(ull*)(g_Ppart + (chunk * 32 + oh * 16 + o) * 1024 + d) = acc[o];
    }
    gsync();

    // ================= Phase B: fold-P (0-31) | bias (32) | MT partials (33-96) =================
    if (blk < 32) {
        __shared__ float sred[32];
        int o = blk;
        float s1 = 0.f, s2 = 0.f;
#pragma unroll
        for (int h = 0; h < 2; h++) {
            int d = tid + h * 512;
            float p = 0.f;
#pragma unroll 16
            for (int c = 0; c < 64; c++) p += g_Ppart[(c * 32 + o) * 1024 + d];
            float pp = nw[d] * p;
            s1 += pp;
            s2 += nb[d] * p;
            g_Pp[d * 32 + o] = pp;
        }
#pragma unroll
        for (int off = 16; off; off >>= 1) {
            s1 += __shfl_down_sync(0xffffffffu, s1, off);
            s2 += __shfl_down_sync(0xffffffffu, s2, off);
        }
        if (lane == 0) { sred[wid] = s1; sred[16 + wid] = s2; }
        __syncthreads();
        if (tid == 0) {
            float S1 = 0.f, S2 = 0.f;
#pragma unroll
            for (int j = 0; j < 16; j++) { S1 += sred[j]; S2 += sred[16 + j]; }
            g_k1[blk] = S1;
            g_k2[blk] = S2;
        }
    } else if (blk == 32) {
        // bias c = b_in @ {A|B}: two 256-thread units
        float* red = dsm + (tid >> 8) * 128;
        int t2 = tid & 255;
        int half = tid >> 8;
        int l2 = t2 & 31, w2 = t2 >> 5;
        const float* G = half ? Bs : A;
        float acc[16];
#pragma unroll
        for (int n = 0; n < 16; n++) acc[n] = 0.f;
        for (int e = t2; e < 2048; e += 256) {
            float bv = b_in[e];
            const float4* g4 = (const float4*)(G + e * 16);
            float4 c0 = g4[0], c1 = g4[1], c2 = g4[2], c3 = g4[3];
            acc[0] += bv * c0.x; acc[1] += bv * c0.y; acc[2] += bv * c0.z; acc[3] += bv * c0.w;
            acc[4] += bv * c1.x; acc[5] += bv * c1.y; acc[6] += bv * c1.z; acc[7] += bv * c1.w;
            acc[8] += bv * c2.x; acc[9] += bv * c2.y; acc[10]+= bv * c2.z; acc[11]+= bv * c2.w;
            acc[12]+= bv * c3.x; acc[13]+= bv * c3.y; acc[14]+= bv * c3.z; acc[15]+= bv * c3.w;
        }
#pragma unroll
        for (int off = 16; off; off >>= 1)
#pragma unroll
            for (int n = 0; n < 16; n++) acc[n] += __shfl_down_sync(0xffffffffu, acc[n], off);
        if (l2 == 0) {
#pragma unroll
            for (int n = 0; n < 16; n++) red[w2 * 16 + n] = acc[n];
        }
        __syncthreads();
        if (t2 < 16) {
            float s = 0.f;
#pragma unroll
            for (int j = 0; j < 8; j++) s += red[j * 16 + t2];
            g_c[half * 16 + t2] = s;
        }
    } else if (blk <= 96) {
        // MT partials: 128 units ; unit covers row-tile(64) x e-octant(256)
        float* sC = dsm + (tid >> 8) * 2048;   // 8KB per unit
        int t2 = tid & 255;
        int unit = (blk - 33) * 2 + (tid >> 8);
        int tile = unit >> 3;        // 0..15 (64 Wout rows)
        int oct = unit & 7;          // 0..7  (256 e)
        int row = tile * 64 + (t2 >> 2);
        int nq = t2 & 3;
        ull acc0 = 0ull, acc1 = 0ull;
        for (int c = 0; c < 2; c++) {
            int e0 = oct * 256 + c * 128;
            __syncthreads();
            for (int i = t2; i < 512; i += 256)
                ((float4*)sC)[i] = ((const float4*)(C + e0 * 16))[i];
            __syncthreads();
            const float* wrow = Wout + row * 2048 + e0;
#pragma unroll 8
            for (int g = 0; g < 32; g++) {
                float4 w4 = *(const float4*)(wrow + g * 4);
#pragma unroll
                for (int j = 0; j < 4; j++) {
                    float wv = (j == 0) ? w4.x : (j == 1) ? w4.y : (j == 2) ? w4.z : w4.w;
                    ull wd = dup_f(wv);
                    ulonglong2 cp = *(const ulonglong2*)(sC + (g * 4 + j) * 16 + nq * 4);
                    FFMA2(acc0, wd, cp.x);
                    FFMA2(acc1, wd, cp.y);
                }
            }
        }
        float a[4];
        unpk(a[0], a[1], acc0);
        unpk(a[2], a[3], acc1);
#pragma unroll
        for (int i = 0; i < 4; i++) {
            int n = nq * 4 + i;
            g_MTp[(oct * 16 + n) * 1024 + row] = a[i];
        }
    }
    gsync();

    // ================= Phase C: LN + projection (output-pair FFMA2, plain P) =================
    {
        float* sXT = dsm;          // 2 x (64 k x 68) = 8704 floats
        float* sP  = dsm + 8704;   // 2 x (64 k x 32) = 4096 floats
        int tg = tid & 15;         // token quad
        int ks = (tid >> 4) & 3;   // k-split
        int og = tid >> 6;         // output quad (warp-uniform)
        int T0 = blk * 64;

        unsigned spb = (unsigned)__cvta_generic_to_shared(sP);

        // prologue: chunk 0
        {
            int row = tid >> 3, col = tid & 7;   // 64 rows x 8 float4
            cp16(spb + (row * 32 + col * 4) * 4, g_Pp + row * 32 + col * 4);
            asm volatile("cp.async.commit_group;");
#pragma unroll
            for (int it = 0; it < 2; it++) {
                int slot = tid + it * 512;
                int k = slot & 63, tq = slot >> 6;
                const float* src = x + (T0 + tq * 4) * 1024 + k;
                *(float4*)&sXT[k * 68 + tq * 4] = make_float4(src[0], src[1024], src[2048], src[3072]);
            }
            asm volatile("cp.async.wait_group 0;");
            __syncthreads();
        }

        ull acc[8] = {0,0,0,0,0,0,0,0};   // [token j][o-pair h] = acc[j*2+h]
        float s1[4] = {0,0,0,0}, s2[4] = {0,0,0,0};
        float xa[2][4];

        for (int c = 0; c < 16; c++) {
            int buf = c & 1;
            if (c < 15) {
                int row = tid >> 3, col = tid & 7;
                cp16(spb + ((buf ^ 1) * 2048 + row * 32 + col * 4) * 4,
                     g_Pp + ((c + 1) * 64 + row) * 32 + col * 4);
                asm volatile("cp.async.commit_group;");
#pragma unroll
                for (int it = 0; it < 2; it++) {
                    int slot = tid + it * 512;
                    int k = slot & 63, tq = slot >> 6;
                    const float* src = x + (T0 + tq * 4) * 1024 + (c + 1) * 64 + k;
                    xa[it][0] = src[0]; xa[it][1] = src[1024];
                    xa[it][2] = src[2048]; xa[it][3] = src[3072];
                }
            }
            const float* xb = sXT + buf * 4352 + tg * 4;
            const float* pb = sP + buf * 2048 + og * 4;
#pragma unroll
            for (int kl = 0; kl < 16; kl++) {
                int k = ks * 16 + kl;
                float4 xv = *(const float4*)(xb + k * 68);
                ulonglong2 pp = *(const ulonglong2*)(pb + k * 32);
                ull x0 = dup_f(xv.x), x1 = dup_f(xv.y), x2 = dup_f(xv.z), x3 = dup_f(xv.w);
                FFMA2(acc[0], x0, pp.x); FFMA2(acc[1], x0, pp.y);
                FFMA2(acc[2], x1, pp.x); FFMA2(acc[3], x1, pp.y);
                FFMA2(acc[4], x2, pp.x); FFMA2(acc[5], x2, pp.y);
                FFMA2(acc[6], x3, pp.x); FFMA2(acc[7], x3, pp.y);
                if (og == 0) {
                    s1[0] += xv.x; s2[0] = fmaf(xv.x, xv.x, s2[0]);
                    s1[1] += xv.y; s2[1] = fmaf(xv.y, xv.y, s2[1]);
                    s1[2] += xv.z; s2[2] = fmaf(xv.z, xv.z, s2[2]);
                    s1[3] += xv.w; s2[3] = fmaf(xv.w, xv.w, s2[3]);
                }
            }
            if (c < 15) {
#pragma unroll
                for (int it = 0; it < 2; it++) {
                    int slot = tid + it * 512;
                    int k = slot & 63, tq = slot >> 6;
                    *(float4*)&sXT[(buf ^ 1) * 4352 + k * 68 + tq * 4] =
                        make_float4(xa[it][0], xa[it][1], xa[it][2], xa[it][3]);
                }
                asm volatile("cp.async.wait_group 0;");
            }
            __syncthreads();
        }

        // ---- combine k-splits + stats + epilogue ----
        float* Acm = dsm;          // 512 x 16
        float* B   = dsm + 8192;   // 64 x 8
        float* Cc  = dsm + 8704;   // mu[64], rs[64]
        if (ks > 0) {
            ull* d8 = (ull*)&Acm[tid * 16];
#pragma unroll
            for (int i = 0; i < 8; i++) d8[i] = acc[i];
        }
        if (og == 0) {
            float* sb = &B[(ks * 16 + tg) * 8];
#pragma unroll
            for (int j = 0; j < 4; j++) { sb[j] = s1[j]; sb[4 + j] = s2[j]; }
        }
        __syncthreads();
        if (tid < 64) {
            int tq = tid >> 2, j = tid & 3;
            float S1 = 0.f, S2 = 0.f;
#pragma unroll
            for (int k2 = 0; k2 < 4; k2++) {
                const float* bb = &B[(k2 * 16 + tq) * 8];
                S1 += bb[j];
                S2 += bb[4 + j];
            }
            float mu = S1 * (1.f / 1024.f);
            float var = S2 * (1.f / 1024.f) - mu * mu;
            Cc[tid] = mu;
            Cc[64 + tid] = rsqrtf(var + 1e-5f);
        }
        if (ks == 0) {
#pragma unroll
            for (int k2 = 1; k2 < 4; k2++) {
                const ull* src = (const ull*)&Acm[(tid + k2 * 16) * 16];
#pragma unroll
                for (int i = 0; i < 8; i++) ADD2(acc[i], src[i]);
            }
        }
        __syncthreads();
        if (ks == 0) {
            float mu[4], rs[4];
#pragma unroll
            for (int j = 0; j < 4; j++) { mu[j] = Cc[tg * 4 + j]; rs[j] = Cc[64 + tg * 4 + j]; }
            int b = T0 >> 12;
            int s0 = (T0 & 4095) + tg * 4;
#pragma unroll
            for (int i = 0; i < 4; i++) {
                int o = og * 4 + i;
                float k1v = g_k1[o];
                float k2v = g_k2[o] + g_c[o];
                float v[4];
#pragma unroll
                for (int j = 0; j < 4; j++) {
                    float lo, hi;
                    unpk(lo, hi, acc[j * 2 + (i >> 1)]);
                    float val = (i & 1) ? hi : lo;
                    val = rs[j] * val - mu[j] * rs[j] * k1v + k2v;
                    if (o < 16) val = 1.f / (1.f + __expf(-val));
                    v[j] = val;
                }
                *(float4*)&g_au[(b * 32 + o) * 4096 + s0] = make_float4(v[0], v[1], v[2], v[3]);
            }
        }
    }
    gsync();

    // ================= Phase D: scan (0-31) | fold-MT (32-63) =================
    if (blk < 32) {
        __shared__ float wA[16], wU[16], pU[16];
        int bn = blk;
        int b = bn >> 4, n = bn & 15;
        const float* ap = g_au + (b * 32 + n) * 4096;
        const float* up = g_au + (b * 32 + 16 + n) * 4096;

        float a[8], u[8];
        const float4* a4 = (const float4*)(ap + tid * 8);
        const float4* u4 = (const float4*)(up + tid * 8);
#pragma unroll
        for (int q = 0; q < 2; q++) {
            float4 av = a4[q], uv = u4[q];
            a[q*4+0] = av.x; a[q*4+1] = av.y; a[q*4+2] = av.z; a[q*4+3] = av.w;
            u[q*4+0] = uv.x; u[q*4+1] = uv.y; u[q*4+2] = uv.z; u[q*4+3] = uv.w;
        }
        float Aloc = 1.f, Uloc = 0.f;
#pragma unroll
        for (int i = 0; i < 8; i++) { Uloc = Uloc * a[i] + u[i]; Aloc *= a[i]; }

        float Ai = Aloc, Ui = Uloc;
#pragma unroll
        for (int off = 1; off < 32; off <<= 1) {
            float Ap = __shfl_up_sync(0xffffffffu, Ai, off);
            float Up = __shfl_up_sync(0xffffffffu, Ui, off);
            if (lane >= off) { Ui = Up * Ai + Ui; Ai = Ap * Ai; }
        }
        if (lane == 31) { wA[wid] = Ai; wU[wid] = Ui; }
        __syncthreads();
        if (tid == 0) {
            float Uc = 0.f;
#pragma unroll
            for (int j = 0; j < 16; j++) {
                pU[j] = Uc;
                Uc = Uc * wA[j] + wU[j];
            }
        }
        __syncthreads();
        float eA = __shfl_up_sync(0xffffffffu, Ai, 1);
        float eU = __shfl_up_sync(0xffffffffu, Ui, 1);
        if (lane == 0) { eA = 1.f; eU = 0.f; }
        float s = pU[wid] * eA + eU;

        float o8[8];
#pragma unroll
        for (int i = 0; i < 8; i++) { s = a[i] * s + u[i]; o8[i] = s; }
        float4* dst = (float4*)(g_states + bn * 4096 + tid * 8);
#pragma unroll
        for (int q = 0; q < 2; q++)
            dst[q] = make_float4(o8[q*4+0], o8[q*4+1], o8[q*4+2], o8[q*4+3]);
    } else if (blk < 64) {
        int base = (blk - 32) * 512 + tid;
        int d = base & 1023, n = base >> 10;
        float s = 0.f;
#pragma unroll
        for (int q = 0; q < 8; q++) s += g_MTp[(q * 16 + n) * 1024 + d];
        g_MT[n * 1024 + d] = s;
    }
    gsync();

    // ================= Phase E: out =================
    {
        float* sST = dsm;   // 64 tokens x 17
        int T0 = blk * 64;
        int b = T0 >> 12, s0 = T0 & 4095;
#pragma unroll
        for (int it = 0; it < 2; it++) {
            int idx = tid + it * 512;
            int soff = idx & 63, n = idx >> 6;
            sST[soff * 17 + n] = g_states[(b * 16 + n) * 4096 + s0 + soff];
        }
        int dq = tid & 255;
        int th = tid >> 8;
        ull m01[16], m23[16];
#pragma unroll
        for (int n = 0; n < 16; n++) {
            ulonglong2 mm = *(const ulonglong2*)(g_MT + n * 1024 + dq * 4);
            m01[n] = mm.x; m23[n] = mm.y;
        }
        ulonglong2 bov = *(const ulonglong2*)(bo + dq * 4);
        __syncthreads();

        for (int tl = 0; tl < 32; tl++) {
            int t = th * 32 + tl;
            ulonglong2 xv = *(const ulonglong2*)(x + (T0 + t) * 1024 + dq * 4);
            ull r01, r23;
            asm("add.rn.f32x2 %0, %1, %2;" : "=l"(r01) : "l"(xv.x), "l"(bov.x));
            asm("add.rn.f32x2 %0, %1, %2;" : "=l"(r23) : "l"(xv.y), "l"(bov.y));
#pragma unroll
            for (int n = 0; n < 16; n++) {
                ull sv = dup_f(sST[t * 17 + n]);
                FFMA2(r01, sv, m01[n]);
                FFMA2(r23, sv, m23[n]);
            }
            ulonglong2 res; res.x = r01; res.y = r23;
            *(ulonglong2*)(out + (T0 + t) * 1024 + dq * 4) = res;
        }
    }
}

// ---------------- launch ----------------
extern "C" void kernel_launch(void* const* d_in, const int* in_sizes, int n_in,
                              void* d_out, int out_size) {
    const float* x    = (const float*)d_in[0];
    const float* nw   = (const float*)d_in[1];
    const float* nb   = (const float*)d_in[2];
    const float* Win  = (const float*)d_in[3];
    const float* b_in = (const float*)d_in[4];
    const float* A    = (const float*)d_in[5];
    const float* Bs   = (const float*)d_in[6];
    const float* C    = (const float*)d_in[7];
    const float* Wout = (const float*)d_in[8];
    const float* bo   = (const float*)d_in[9];
    float* out = (float*)d_out;

    cudaFuncSetAttribute(k_main, cudaFuncAttributeMaxDynamicSharedMemorySize, 69632);

    k_main<<<GRID, NT, 67584>>>(x, nw, nb, Win, b_in, A, Bs, C, Wout, bo, out);
}

// round 15
// speedup vs baseline: 1.3095x; 1.0663x over previous
#include <cuda_runtime.h>
#include <math.h>

#define GRID 256
#define NT 256

// ---------------- scratch ----------------
__device__ __align__(16) float g_Ppart[64 * 32 * 1024]; // [chunk(64)][o][d]  (L2-resident)
__device__ __align__(16) float g_MTp[8 * 16 * 1024];    // [oct(8)][n][d]
__device__ __align__(16) float g_Pp[1024 * 32];         // [k][o] plain
__device__ __align__(16) float g_MT[16 * 1024];         // [n][d]
__device__ float g_c[32];
__device__ float g_k1[32];
__device__ float g_k2[32];
__device__ __align__(16) float g_au[2 * 32 * 4096];     // [b][o][s]
__device__ __align__(16) float g_states[2 * 16 * 4096]; // [b*16+n][s]
__device__ int g_cnt;                                   // barrier (monotonic)

typedef unsigned long long ull;
__device__ __forceinline__ ull dup_f(float v) {
    ull r; asm("mov.b64 %0, {%1, %1};" : "=l"(r) : "f"(v)); return r;
}
#define FFMA2(acc, a, b) asm("fma.rn.f32x2 %0, %1, %2, %0;" : "+l"(acc) : "l"(a), "l"(b))
#define ADD2(acc, a)     asm("add.rn.f32x2 %0, %0, %1;" : "+l"(acc) : "l"(a))
__device__ __forceinline__ void unpk(float& lo, float& hi, ull v) {
    asm("mov.b64 {%0, %1}, %2;" : "=f"(lo), "=f"(hi) : "l"(v));
}
__device__ __forceinline__ void cp16(unsigned int dst, const void* src) {
    asm volatile("cp.async.ca.shared.global [%0], [%1], 16;" :: "r"(dst), "l"(src));
}

// grid-wide barrier: monotonic counter, replay-safe
__device__ __forceinline__ void gsync() {
    __syncthreads();
    if (threadIdx.x == 0) {
        __threadfence();
        int arrival = atomicAdd(&g_cnt, 1);
        int target = (arrival / GRID + 1) * GRID;
        while (*((volatile int*)&g_cnt) < target) { }
        __threadfence();
    }
    __syncthreads();
}

// ---------------- single fused kernel ----------------
__global__ void __launch_bounds__(NT, 2) k_main(const float* __restrict__ x,
                                                const float* __restrict__ nw,
                                                const float* __restrict__ nb,
                                                const float* __restrict__ Win,
                                                const float* __restrict__ b_in,
                                                const float* __restrict__ A,
                                                const float* __restrict__ Bs,
                                                const float* __restrict__ C,
                                                const float* __restrict__ Wout,
                                                const float* __restrict__ bo,
                                                float* __restrict__ out) {
    extern __shared__ float dsm[];   // 8704 floats = 34816 B
    int tid = threadIdx.x;
    int blk = blockIdx.x;
    int lane = tid & 31, wid = tid >> 5;

    // ================= Phase A: P split-K partials, 1 unit per block =================
    {
        ull* sAB2 = (ull*)dsm;       // 512 pairs = 8KB
        int dt = blk >> 6;           // 0..3  (d-tile of 256)
        int chunk = blk & 63;        // 0..63 (e-chunk of 32)
        int e0 = chunk * 32;
        for (int i = tid; i < 512; i += 256) {
            int el = i >> 4, n = i & 15;
            sAB2[el * 32 + n]      = dup_f(A [(e0 + el) * 16 + n]);
            sAB2[el * 32 + 16 + n] = dup_f(Bs[(e0 + el) * 16 + n]);
        }
        __syncthreads();
        int dp = tid >> 1, oh = tid & 1;
        int d = dt * 256 + dp * 2;
        ull acc[16];
#pragma unroll
        for (int o = 0; o < 16; o++) acc[o] = 0ull;
#pragma unroll
        for (int b8 = 0; b8 < 4; b8++) {
            ull w[8];
#pragma unroll
            for (int i = 0; i < 8; i++)
                w[i] = *(const ull*)(Win + (e0 + b8 * 8 + i) * 1024 + d);
#pragma unroll
            for (int i = 0; i < 8; i++) {
                const ull* base = sAB2 + (b8 * 8 + i) * 32 + oh * 16;
#pragma unroll
                for (int o = 0; o < 16; o++) FFMA2(acc[o], w[i], base[o]);
            }
        }
#pragma unroll
        for (int o = 0; o < 16; o++)
            *(ull*)(g_Ppart + (chunk * 32 + oh * 16 + o) * 1024 + d) = acc[o];
    }
    gsync();

    // ================= Phase B: fold-P (0-31) | bias (32,33) | MT partials (34-161) =========
    if (blk < 32) {
        __shared__ float sred[16];
        int o = blk;
        float s1 = 0.f, s2 = 0.f;
#pragma unroll
        for (int h = 0; h < 4; h++) {
            int d = tid + h * 256;
            float p = 0.f;
#pragma unroll 16
            for (int c = 0; c < 64; c++) p += g_Ppart[(c * 32 + o) * 1024 + d];
            float pp = nw[d] * p;
            s1 += pp;
            s2 += nb[d] * p;
            g_Pp[d * 32 + o] = pp;
        }
#pragma unroll
        for (int off = 16; off; off >>= 1) {
            s1 += __shfl_down_sync(0xffffffffu, s1, off);
            s2 += __shfl_down_sync(0xffffffffu, s2, off);
        }
        if (lane == 0) { sred[wid] = s1; sred[8 + wid] = s2; }
        __syncthreads();
        if (tid == 0) {
            float S1 = 0.f, S2 = 0.f;
#pragma unroll
            for (int j = 0; j < 8; j++) { S1 += sred[j]; S2 += sred[8 + j]; }
            g_k1[blk] = S1;
            g_k2[blk] = S2;
        }
    } else if (blk < 34) {
        // bias c = b_in @ {A|B}
        float* red = dsm;
        int half = blk - 32;
        const float* G = half ? Bs : A;
        float acc[16];
#pragma unroll
        for (int n = 0; n < 16; n++) acc[n] = 0.f;
        for (int e = tid; e < 2048; e += 256) {
            float bv = b_in[e];
            const float4* g4 = (const float4*)(G + e * 16);
            float4 c0 = g4[0], c1 = g4[1], c2 = g4[2], c3 = g4[3];
            acc[0] += bv * c0.x; acc[1] += bv * c0.y; acc[2] += bv * c0.z; acc[3] += bv * c0.w;
            acc[4] += bv * c1.x; acc[5] += bv * c1.y; acc[6] += bv * c1.z; acc[7] += bv * c1.w;
            acc[8] += bv * c2.x; acc[9] += bv * c2.y; acc[10]+= bv * c2.z; acc[11]+= bv * c2.w;
            acc[12]+= bv * c3.x; acc[13]+= bv * c3.y; acc[14]+= bv * c3.z; acc[15]+= bv * c3.w;
        }
#pragma unroll
        for (int off = 16; off; off >>= 1)
#pragma unroll
            for (int n = 0; n < 16; n++) acc[n] += __shfl_down_sync(0xffffffffu, acc[n], off);
        if (lane == 0) {
#pragma unroll
            for (int n = 0; n < 16; n++) red[wid * 16 + n] = acc[n];
        }
        __syncthreads();
        if (tid < 16) {
            float s = 0.f;
#pragma unroll
            for (int j = 0; j < 8; j++) s += red[j * 16 + tid];
            g_c[half * 16 + tid] = s;
        }
    } else if (blk < 162) {
        // MT partials: unit covers row-tile(64) x e-octant(256)
        float* sC = dsm;             // 8KB
        int unit = blk - 34;
        int tile = unit >> 3;        // 0..15 (64 Wout rows)
        int oct = unit & 7;          // 0..7  (256 e)
        int row = tile * 64 + (tid >> 2);
        int nq = tid & 3;
        ull acc0 = 0ull, acc1 = 0ull;
        for (int c = 0; c < 2; c++) {
            int e0 = oct * 256 + c * 128;
            __syncthreads();
            for (int i = tid; i < 512; i += 256)
                ((float4*)sC)[i] = ((const float4*)(C + e0 * 16))[i];
            __syncthreads();
            const float* wrow = Wout + row * 2048 + e0;
#pragma unroll 8
            for (int g = 0; g < 32; g++) {
                float4 w4 = *(const float4*)(wrow + g * 4);
#pragma unroll
                for (int j = 0; j < 4; j++) {
                    float wv = (j == 0) ? w4.x : (j == 1) ? w4.y : (j == 2) ? w4.z : w4.w;
                    ull wd = dup_f(wv);
                    ulonglong2 cp = *(const ulonglong2*)(sC + (g * 4 + j) * 16 + nq * 4);
                    FFMA2(acc0, wd, cp.x);
                    FFMA2(acc1, wd, cp.y);
                }
            }
        }
        float a[4];
        unpk(a[0], a[1], acc0);
        unpk(a[2], a[3], acc1);
#pragma unroll
        for (int i = 0; i < 4; i++) {
            int n = nq * 4 + i;
            g_MTp[(oct * 16 + n) * 1024 + row] = a[i];
        }
    }
    gsync();

    // ================= Phase C: LN + projection, 32 tokens/block =================
    {
        float* sXT = dsm;          // 2 x (64 k x 36) = 4608 floats
        float* sP  = dsm + 4608;   // 2 x (64 k x 32) = 4096 floats
        int tg = tid & 7;          // token quad (8 quads = 32 tokens)
        int ks = (tid >> 3) & 3;   // k-split
        int og = tid >> 5;         // output quad (warp-uniform)
        int T0 = blk * 32;

        unsigned spb = (unsigned)__cvta_generic_to_shared(sP);

        // prologue: chunk 0
        {
#pragma unroll
            for (int it = 0; it < 2; it++) {
                int slot = tid + it * 256;
                int row = slot >> 3, col = slot & 7;   // 64 rows x 8 float4
                cp16(spb + (row * 32 + col * 4) * 4, g_Pp + row * 32 + col * 4);
            }
            asm volatile("cp.async.commit_group;");
#pragma unroll
            for (int it = 0; it < 2; it++) {
                int slot = tid + it * 256;
                int k = slot & 63, tq = slot >> 6;     // 8 token quads
                const float* src = x + (T0 + tq * 4) * 1024 + k;
                *(float4*)&sXT[k * 36 + tq * 4] = make_float4(src[0], src[1024], src[2048], src[3072]);
            }
            asm volatile("cp.async.wait_group 0;");
            __syncthreads();
        }

        ull acc[8] = {0,0,0,0,0,0,0,0};   // [token j][o-pair h]
        float s1[4] = {0,0,0,0}, s2[4] = {0,0,0,0};
        float xa[2][4];

        for (int c = 0; c < 16; c++) {
            int buf = c & 1;
            if (c < 15) {
#pragma unroll
                for (int it = 0; it < 2; it++) {
                    int slot = tid + it * 256;
                    int row = slot >> 3, col = slot & 7;
                    cp16(spb + ((buf ^ 1) * 2048 + row * 32 + col * 4) * 4,
                         g_Pp + ((c + 1) * 64 + row) * 32 + col * 4);
                }
                asm volatile("cp.async.commit_group;");
#pragma unroll
                for (int it = 0; it < 2; it++) {
                    int slot = tid + it * 256;
                    int k = slot & 63, tq = slot >> 6;
                    const float* src = x + (T0 + tq * 4) * 1024 + (c + 1) * 64 + k;
                    xa[it][0] = src[0]; xa[it][1] = src[1024];
                    xa[it][2] = src[2048]; xa[it][3] = src[3072];
                }
            }
            const float* xb = sXT + buf * 2304 + tg * 4;
            const float* pb = sP + buf * 2048 + og * 4;
#pragma unroll
            for (int kl = 0; kl < 16; kl++) {
                int k = ks * 16 + kl;
                float4 xv = *(const float4*)(xb + k * 36);
                ulonglong2 pp = *(const ulonglong2*)(pb + k * 32);
                ull x0 = dup_f(xv.x), x1 = dup_f(xv.y), x2 = dup_f(xv.z), x3 = dup_f(xv.w);
                FFMA2(acc[0], x0, pp.x); FFMA2(acc[1], x0, pp.y);
                FFMA2(acc[2], x1, pp.x); FFMA2(acc[3], x1, pp.y);
                FFMA2(acc[4], x2, pp.x); FFMA2(acc[5], x2, pp.y);
                FFMA2(acc[6], x3, pp.x); FFMA2(acc[7], x3, pp.y);
                if (og == 0) {
                    s1[0] += xv.x; s2[0] = fmaf(xv.x, xv.x, s2[0]);
                    s1[1] += xv.y; s2[1] = fmaf(xv.y, xv.y, s2[1]);
                    s1[2] += xv.z; s2[2] = fmaf(xv.z, xv.z, s2[2]);
                    s1[3] += xv.w; s2[3] = fmaf(xv.w, xv.w, s2[3]);
                }
            }
            if (c < 15) {
#pragma unroll
                for (int it = 0; it < 2; it++) {
                    int slot = tid + it * 256;
                    int k = slot & 63, tq = slot >> 6;
                    *(float4*)&sXT[(buf ^ 1) * 2304 + k * 36 + tq * 4] =
                        make_float4(xa[it][0], xa[it][1], xa[it][2], xa[it][3]);
                }
                asm volatile("cp.async.wait_group 0;");
            }
            __syncthreads();
        }

        // ---- combine k-splits + stats + epilogue ----
        float* Acm = dsm;          // 256 slots x 16 = 4096 floats
        float* B   = dsm + 4096;   // 32 slots x 8 = 256 floats
        float* Cc  = dsm + 4352;   // mu[32], rs[32]
        if (ks > 0) {
            ull* d8 = (ull*)&Acm[tid * 16];
#pragma unroll
            for (int i = 0; i < 8; i++) d8[i] = acc[i];
        }
        if (og == 0) {
            float* sb = &B[(ks * 8 + tg) * 8];
#pragma unroll
            for (int j = 0; j < 4; j++) { sb[j] = s1[j]; sb[4 + j] = s2[j]; }
        }
        __syncthreads();
        if (tid < 32) {
            int tq = tid >> 2, j = tid & 3;
            float S1 = 0.f, S2 = 0.f;
#pragma unroll
            for (int k2 = 0; k2 < 4; k2++) {
                const float* bb = &B[(k2 * 8 + tq) * 8];
                S1 += bb[j];
                S2 += bb[4 + j];
            }
            float mu = S1 * (1.f / 1024.f);
            float var = S2 * (1.f / 1024.f) - mu * mu;
            Cc[tid] = mu;
            Cc[32 + tid] = rsqrtf(var + 1e-5f);
        }
        if (ks == 0) {
#pragma unroll
            for (int k2 = 1; k2 < 4; k2++) {
                const ull* src = (const ull*)&Acm[(tid + k2 * 8) * 16];
#pragma unroll
                for (int i = 0; i < 8; i++) ADD2(acc[i], src[i]);
            }
        }
        __syncthreads();
        if (ks == 0) {
            float mu[4], rs[4];
#pragma unroll
            for (int j = 0; j < 4; j++) { mu[j] = Cc[tg * 4 + j]; rs[j] = Cc[32 + tg * 4 + j]; }
            int b = T0 >> 12;
            int s0 = (T0 & 4095) + tg * 4;
#pragma unroll
            for (int i = 0; i < 4; i++) {
                int o = og * 4 + i;
                float k1v = g_k1[o];
                float k2v = g_k2[o] + g_c[o];
                float v[4];
#pragma unroll
                for (int j = 0; j < 4; j++) {
                    float lo, hi;
                    unpk(lo, hi, acc[j * 2 + (i >> 1)]);
                    float val = (i & 1) ? hi : lo;
                    val = rs[j] * val - mu[j] * rs[j] * k1v + k2v;
                    if (o < 16) val = 1.f / (1.f + __expf(-val));
                    v[j] = val;
                }
                *(float4*)&g_au[(b * 32 + o) * 4096 + s0] = make_float4(v[0], v[1], v[2], v[3]);
            }
        }
    }
    gsync();

    // ================= Phase D: scan (0-31) | fold-MT (32-63) =================
    if (blk < 32) {
        __shared__ float wA[8], wU[8], pU[8];
        int bn = blk;
        int b = bn >> 4, n = bn & 15;
        const float* ap = g_au + (b * 32 + n) * 4096;
        const float* up = g_au + (b * 32 + 16 + n) * 4096;

        float a[16], u[16];
        const float4* a4 = (const float4*)(ap + tid * 16);
        const float4* u4 = (const float4*)(up + tid * 16);
#pragma unroll
        for (int q = 0; q < 4; q++) {
            float4 av = a4[q], uv = u4[q];
            a[q*4+0] = av.x; a[q*4+1] = av.y; a[q*4+2] = av.z; a[q*4+3] = av.w;
            u[q*4+0] = uv.x; u[q*4+1] = uv.y; u[q*4+2] = uv.z; u[q*4+3] = uv.w;
        }
        float Aloc = 1.f, Uloc = 0.f;
#pragma unroll
        for (int i = 0; i < 16; i++) { Uloc = Uloc * a[i] + u[i]; Aloc *= a[i]; }

        float Ai = Aloc, Ui = Uloc;
#pragma unroll
        for (int off = 1; off < 32; off <<= 1) {
            float Ap = __shfl_up_sync(0xffffffffu, Ai, off);
            float Up = __shfl_up_sync(0xffffffffu, Ui, off);
            if (lane >= off) { Ui = Up * Ai + Ui; Ai = Ap * Ai; }
        }
        if (lane == 31) { wA[wid] = Ai; wU[wid] = Ui; }
        __syncthreads();
        if (tid == 0) {
            float Uc = 0.f;
#pragma unroll
            for (int j = 0; j < 8; j++) {
                pU[j] = Uc;
                Uc = Uc * wA[j] + wU[j];
            }
        }
        __syncthreads();
        float eA = __shfl_up_sync(0xffffffffu, Ai, 1);
        float eU = __shfl_up_sync(0xffffffffu, Ui, 1);
        if (lane == 0) { eA = 1.f; eU = 0.f; }
        float s = pU[wid] * eA + eU;

        float o16[16];
#pragma unroll
        for (int i = 0; i < 16; i++) { s = a[i] * s + u[i]; o16[i] = s; }
        float4* dst = (float4*)(g_states + bn * 4096 + tid * 16);
#pragma unroll
        for (int q = 0; q < 4; q++)
            dst[q] = make_float4(o16[q*4+0], o16[q*4+1], o16[q*4+2], o16[q*4+3]);
    } else if (blk < 64) {
#pragma unroll
        for (int h = 0; h < 2; h++) {
            int base = (blk - 32) * 512 + h * 256 + tid;
            int d = base & 1023, n = base >> 10;
            float s = 0.f;
#pragma unroll
            for (int q = 0; q < 8; q++) s += g_MTp[(q * 16 + n) * 1024 + d];
            g_MT[n * 1024 + d] = s;
        }
    }
    gsync();

    // ================= Phase E: out, 32 tokens/block =================
    {
        float* sST = dsm;   // 32 tokens x 17
        int T0 = blk * 32;
        int b = T0 >> 12, s0 = T0 & 4095;
#pragma unroll
        for (int it = 0; it < 2; it++) {
            int idx = tid + it * 256;
            int soff = idx & 31, n = idx >> 5;
            sST[soff * 17 + n] = g_states[(b * 16 + n) * 4096 + s0 + soff];
        }
        ull m01[16], m23[16];
#pragma unroll
        for (int n = 0; n < 16; n++) {
            ulonglong2 mm = *(const ulonglong2*)(g_MT + n * 1024 + tid * 4);
            m01[n] = mm.x; m23[n] = mm.y;
        }
        ulonglong2 bov = *(const ulonglong2*)(bo + tid * 4);
        __syncthreads();

        for (int t = 0; t < 32; t++) {
            ulonglong2 xv = *(const ulonglong2*)(x + (T0 + t) * 1024 + tid * 4);
            ull r01, r23;
            asm("add.rn.f32x2 %0, %1, %2;" : "=l"(r01) : "l"(xv.x), "l"(bov.x));
            asm("add.rn.f32x2 %0, %1, %2;" : "=l"(r23) : "l"(xv.y), "l"(bov.y));
#pragma unroll
            for (int n = 0; n < 16; n++) {
                ull sv = dup_f(sST[t * 17 + n]);
                FFMA2(r01, sv, m01[n]);
                FFMA2(r23, sv, m23[n]);
            }
            ulonglong2 res; res.x = r01; res.y = r23;
            *(ulonglong2*)(out + (T0 + t) * 1024 + tid * 4) = res;
        }
    }
}

// ---------------- launch ----------------
extern "C" void kernel_launch(void* const* d_in, const int* in_sizes, int n_in,
                              void* d_out, int out_size) {
    const float* x    = (const float*)d_in[0];
    const float* nw   = (const float*)d_in[1];
    const float* nb   = (const float*)d_in[2];
    const float* Win  = (const float*)d_in[3];
    const float* b_in = (const float*)d_in[4];
    const float* A    = (const float*)d_in[5];
    const float* Bs   = (const float*)d_in[6];
    const float* C    = (const float*)d_in[7];
    const float* Wout = (const float*)d_in[8];
    const float* bo   = (const float*)d_in[9];
    float* out = (float*)d_out;

    cudaFuncSetAttribute(k_main, cudaFuncAttributeMaxDynamicSharedMemorySize, 34816);

    k_main<<<GRID, NT, 34816>>>(x, nw, nb, Win, b_in, A, Bs, C, Wout, bo, out);
}

// round 17
// speedup vs baseline: 1.3147x; 1.0040x over previous
#include <cuda_runtime.h>
#include <math.h>

#define GRID 256
#define NT 256

// ---------------- scratch ----------------
__device__ __align__(16) float g_Ppart[64 * 32 * 1024]; // [chunk(64)][o][d]
__device__ __align__(16) float g_MTp[8 * 16 * 1024];    // [oct(8)][n][d]
__device__ __align__(16) float g_Pp[1024 * 32];         // [k][o]
__device__ __align__(16) float g_MT[16 * 1024];         // [n][d]
__device__ float g_c[32];
__device__ float g_k1[32];
__device__ float g_k2[32];
__device__ __align__(16) float g_au[2 * 32 * 4096];     // [b][o][s]
__device__ __align__(16) float g_states[2 * 16 * 4096]; // [b*16+n][s]
__device__ int g_cnt;

typedef unsigned long long ull;
__device__ __forceinline__ ull dup_f(float v) {
    ull r; asm("mov.b64 %0, {%1, %1};" : "=l"(r) : "f"(v)); return r;
}
__device__ __forceinline__ ull pack2(float a, float b) {
    ull r; asm("mov.b64 %0, {%1, %2};" : "=l"(r) : "f"(a), "f"(b)); return r;
}
#define FFMA2(acc, a, b) asm("fma.rn.f32x2 %0, %1, %2, %0;" : "+l"(acc) : "l"(a), "l"(b))
#define ADD2(acc, a)     asm("add.rn.f32x2 %0, %0, %1;" : "+l"(acc) : "l"(a))
__device__ __forceinline__ void unpk(float& lo, float& hi, ull v) {
    asm("mov.b64 {%0, %1}, %2;" : "=f"(lo), "=f"(hi) : "l"(v));
}
__device__ __forceinline__ void cp16(unsigned int dst, const void* src) {
    asm volatile("cp.async.ca.shared.global [%0], [%1], 16;" :: "r"(dst), "l"(src));
}

__device__ __forceinline__ void gsync() {
    __syncthreads();
    if (threadIdx.x == 0) {
        __threadfence();
        int arrival = atomicAdd(&g_cnt, 1);
        int target = (arrival / GRID + 1) * GRID;
        while (*((volatile int*)&g_cnt) < target) { }
        __threadfence();
    }
    __syncthreads();
}

// ---------------- single fused kernel ----------------
__global__ void __launch_bounds__(NT, 2) k_main(const float* __restrict__ x,
                                                const float* __restrict__ nw,
                                                const float* __restrict__ nb,
                                                const float* __restrict__ Win,
                                                const float* __restrict__ b_in,
                                                const float* __restrict__ A,
                                                const float* __restrict__ Bs,
                                                const float* __restrict__ C,
                                                const float* __restrict__ Wout,
                                                const float* __restrict__ bo,
                                                float* __restrict__ out) {
    extern __shared__ float dsm[];   // 8704 floats = 34816 B
    __shared__ float sMu[32], sRs[32];
    int tid = threadIdx.x;
    int blk = blockIdx.x;
    int lane = tid & 31, wid = tid >> 5;

    // ================= Phase A: P split-K partials, 1 unit per block =================
    {
        ull* sAB2 = (ull*)dsm;
        int dt = blk >> 6;
        int chunk = blk & 63;
        int e0 = chunk * 32;
        for (int i = tid; i < 512; i += 256) {
            int el = i >> 4, n = i & 15;
            sAB2[el * 32 + n]      = dup_f(A [(e0 + el) * 16 + n]);
            sAB2[el * 32 + 16 + n] = dup_f(Bs[(e0 + el) * 16 + n]);
        }
        __syncthreads();
        int dp = tid >> 1, oh = tid & 1;
        int d = dt * 256 + dp * 2;
        ull acc[16];
#pragma unroll
        for (int o = 0; o < 16; o++) acc[o] = 0ull;
#pragma unroll
        for (int b8 = 0; b8 < 4; b8++) {
            ull w[8];
#pragma unroll
            for (int i = 0; i < 8; i++)
                w[i] = *(const ull*)(Win + (e0 + b8 * 8 + i) * 1024 + d);
#pragma unroll
            for (int i = 0; i < 8; i++) {
                const ull* base = sAB2 + (b8 * 8 + i) * 32 + oh * 16;
#pragma unroll
                for (int o = 0; o < 16; o++) FFMA2(acc[o], w[i], base[o]);
            }
        }
#pragma unroll
        for (int o = 0; o < 16; o++)
            *(ull*)(g_Ppart + (chunk * 32 + oh * 16 + o) * 1024 + d) = acc[o];
    }
    gsync();

    // ================= Phase B: fold-P (0-31) | bias (32,33) | MT partials (34-161) =========
    if (blk < 32) {
        __shared__ float sred[16];
        int o = blk;
        float s1 = 0.f, s2 = 0.f;
#pragma unroll
        for (int h = 0; h < 4; h++) {
            int d = tid + h * 256;
            float p = 0.f;
#pragma unroll 16
            for (int c = 0; c < 64; c++) p += g_Ppart[(c * 32 + o) * 1024 + d];
            float pp = nw[d] * p;
            s1 += pp;
            s2 += nb[d] * p;
            g_Pp[d * 32 + o] = pp;
        }
#pragma unroll
        for (int off = 16; off; off >>= 1) {
            s1 += __shfl_down_sync(0xffffffffu, s1, off);
            s2 += __shfl_down_sync(0xffffffffu, s2, off);
        }
        if (lane == 0) { sred[wid] = s1; sred[8 + wid] = s2; }
        __syncthreads();
        if (tid == 0) {
            float S1 = 0.f, S2 = 0.f;
#pragma unroll
            for (int j = 0; j < 8; j++) { S1 += sred[j]; S2 += sred[8 + j]; }
            g_k1[blk] = S1;
            g_k2[blk] = S2;
        }
    } else if (blk < 34) {
        float* red = dsm;
        int half = blk - 32;
        const float* G = half ? Bs : A;
        float acc[16];
#pragma unroll
        for (int n = 0; n < 16; n++) acc[n] = 0.f;
        for (int e = tid; e < 2048; e += 256) {
            float bv = b_in[e];
            const float4* g4 = (const float4*)(G + e * 16);
            float4 c0 = g4[0], c1 = g4[1], c2 = g4[2], c3 = g4[3];
            acc[0] += bv * c0.x; acc[1] += bv * c0.y; acc[2] += bv * c0.z; acc[3] += bv * c0.w;
            acc[4] += bv * c1.x; acc[5] += bv * c1.y; acc[6] += bv * c1.z; acc[7] += bv * c1.w;
            acc[8] += bv * c2.x; acc[9] += bv * c2.y; acc[10]+= bv * c2.z; acc[11]+= bv * c2.w;
            acc[12]+= bv * c3.x; acc[13]+= bv * c3.y; acc[14]+= bv * c3.z; acc[15]+= bv * c3.w;
        }
#pragma unroll
        for (int off = 16; off; off >>= 1)
#pragma unroll
            for (int n = 0; n < 16; n++) acc[n] += __shfl_down_sync(0xffffffffu, acc[n], off);
        if (lane == 0) {
#pragma unroll
            for (int n = 0; n < 16; n++) red[wid * 16 + n] = acc[n];
        }
        __syncthreads();
        if (tid < 16) {
            float s = 0.f;
#pragma unroll
            for (int j = 0; j < 8; j++) s += red[j * 16 + tid];
            g_c[half * 16 + tid] = s;
        }
    } else if (blk < 162) {
        float* sC = dsm;
        int unit = blk - 34;
        int tile = unit >> 3;
        int oct = unit & 7;
        int row = tile * 64 + (tid >> 2);
        int nq = tid & 3;
        ull acc0 = 0ull, acc1 = 0ull;
        for (int c = 0; c < 2; c++) {
            int e0 = oct * 256 + c * 128;
            __syncthreads();
            for (int i = tid; i < 512; i += 256)
                ((float4*)sC)[i] = ((const float4*)(C + e0 * 16))[i];
            __syncthreads();
            const float* wrow = Wout + row * 2048 + e0;
#pragma unroll 8
            for (int g = 0; g < 32; g++) {
                float4 w4 = *(const float4*)(wrow + g * 4);
#pragma unroll
                for (int j = 0; j < 4; j++) {
                    float wv = (j == 0) ? w4.x : (j == 1) ? w4.y : (j == 2) ? w4.z : w4.w;
                    ull wd = dup_f(wv);
                    ulonglong2 cp = *(const ulonglong2*)(sC + (g * 4 + j) * 16 + nq * 4);
                    FFMA2(acc0, wd, cp.x);
                    FFMA2(acc1, wd, cp.y);
                }
            }
        }
        float a[4];
        unpk(a[0], a[1], acc0);
        unpk(a[2], a[3], acc1);
#pragma unroll
        for (int i = 0; i < 4; i++) {
            int n = nq * 4 + i;
            g_MTp[(oct * 16 + n) * 1024 + row] = a[i];
        }
    }
    gsync();

    // ================= Phase C: LN + projection, warp-uniform k mapping =================
    {
        float* sXT = dsm;          // 2 x (64 k x 36) = 4608 floats
        float* sP  = dsm + 4608;   // 2 x (64 k x 32) = 4096 floats
        int ks  = wid >> 1;        // warp-uniform k-split (0..3)
        int owh = wid & 1;
        int tg  = lane & 7;        // token quad 0..7
        int oh  = lane >> 3;       // 0..3
        int og  = owh * 4 + oh;    // output quad 0..7
        int T0 = blk * 32;

        unsigned spb = (unsigned)__cvta_generic_to_shared(sP);

        // loader stats (packed pairs): st1/st2 [it*2+p]
        ull st1[4] = {0,0,0,0}, st2[4] = {0,0,0,0};

        // prologue: chunk 0
        {
#pragma unroll
            for (int it = 0; it < 2; it++) {
                int slot = tid + it * 256;
                int row = slot >> 3, col = slot & 7;
                cp16(spb + (row * 32 + col * 4) * 4, g_Pp + row * 32 + col * 4);
            }
            asm volatile("cp.async.commit_group;");
#pragma unroll
            for (int it = 0; it < 2; it++) {
                int slot = tid + it * 256;
                int k = slot & 63, tq = slot >> 6;
                const float* src = x + (T0 + tq * 4) * 1024 + k;
                float a0 = src[0], a1 = src[1024], a2 = src[2048], a3 = src[3072];
                *(float4*)&sXT[k * 36 + tq * 4] = make_float4(a0, a1, a2, a3);
                ull p01 = pack2(a0, a1), p23 = pack2(a2, a3);
                ADD2(st1[it * 2], p01); ADD2(st1[it * 2 + 1], p23);
                FFMA2(st2[it * 2], p01, p01); FFMA2(st2[it * 2 + 1], p23, p23);
            }
            asm volatile("cp.async.wait_group 0;");
            __syncthreads();
        }

        ull acc[8] = {0,0,0,0,0,0,0,0};   // [token j][o-pair h]
        float xa[2][4];

        for (int c = 0; c < 16; c++) {
            int buf = c & 1;
            if (c < 15) {
#pragma unroll
                for (int it = 0; it < 2; it++) {
                    int slot = tid + it * 256;
                    int row = slot >> 3, col = slot & 7;
                    cp16(spb + ((buf ^ 1) * 2048 + row * 32 + col * 4) * 4,
                         g_Pp + ((c + 1) * 64 + row) * 32 + col * 4);
                }
                asm volatile("cp.async.commit_group;");
#pragma unroll
                for (int it = 0; it < 2; it++) {
                    int slot = tid + it * 256;
                    int k = slot & 63, tq = slot >> 6;
                    const float* src = x + (T0 + tq * 4) * 1024 + (c + 1) * 64 + k;
                    xa[it][0] = src[0]; xa[it][1] = src[1024];
                    xa[it][2] = src[2048]; xa[it][3] = src[3072];
                }
            }
            const float* xb = sXT + buf * 2304 + tg * 4;
            const float* pb = sP + buf * 2048 + og * 4;
#pragma unroll
            for (int kl = 0; kl < 16; kl++) {
                int k = ks * 16 + kl;
                float4 xv = *(const float4*)(xb + k * 36);
                ulonglong2 pp = *(const ulonglong2*)(pb + k * 32);
                ull x0 = dup_f(xv.x), x1 = dup_f(xv.y), x2 = dup_f(xv.z), x3 = dup_f(xv.w);
                FFMA2(acc[0], x0, pp.x); FFMA2(acc[1], x0, pp.y);
                FFMA2(acc[2], x1, pp.x); FFMA2(acc[3], x1, pp.y);
                FFMA2(acc[4], x2, pp.x); FFMA2(acc[5], x2, pp.y);
                FFMA2(acc[6], x3, pp.x); FFMA2(acc[7], x3, pp.y);
            }
            if (c < 15) {
#pragma unroll
                for (int it = 0; it < 2; it++) {
                    int slot = tid + it * 256;
                    int k = slot & 63, tq = slot >> 6;
                    *(float4*)&sXT[(buf ^ 1) * 2304 + k * 36 + tq * 4] =
                        make_float4(xa[it][0], xa[it][1], xa[it][2], xa[it][3]);
                    ull p01 = pack2(xa[it][0], xa[it][1]), p23 = pack2(xa[it][2], xa[it][3]);
                    ADD2(st1[it * 2], p01); ADD2(st1[it * 2 + 1], p23);
                    FFMA2(st2[it * 2], p01, p01); FFMA2(st2[it * 2 + 1], p23, p23);
                }
                asm volatile("cp.async.wait_group 0;");
            }
            __syncthreads();
        }

        // ---- stats: warp shfl-reduce (f32x2 adds!) + cross-warp combine ----
#pragma unroll
        for (int off = 16; off; off >>= 1) {
#pragma unroll
            for (int i = 0; i < 4; i++) {
                ull t1 = __shfl_down_sync(0xffffffffu, st1[i], off);
                ull t2 = __shfl_down_sync(0xffffffffu, st2[i], off);
                ADD2(st1[i], t1);
                ADD2(st2[i], t2);
            }
        }
        ull* sWst = (ull*)(dsm + 3072);   // 8 warps x 8 ull
        if (lane == 0) {
            ull* w8 = &sWst[wid * 8];
#pragma unroll
            for (int i = 0; i < 4; i++) { w8[i] = st1[i]; w8[4 + i] = st2[i]; }
        }
        // ---- k-split combine: ks>0 dump acc ----
        if (ks > 0) {
            ull* d8 = (ull*)&dsm[((ks - 1) * 64 + owh * 32 + oh * 8 + tg) * 16];
#pragma unroll
            for (int i = 0; i < 8; i++) d8[i] = acc[i];
        }
        __syncthreads();
        if (tid < 32) {
            int tk = tid;
            int g = (tk >> 2) & 3, it = tk >> 4, j = tk & 3;
            int p = j >> 1, hi = j & 1;
            ull u1 = sWst[(2 * g) * 8 + it * 2 + p];
            ADD2(u1, sWst[(2 * g + 1) * 8 + it * 2 + p]);
            ull u2 = sWst[(2 * g) * 8 + 4 + it * 2 + p];
            ADD2(u2, sWst[(2 * g + 1) * 8 + 4 + it * 2 + p]);
            float lo1, hi1, lo2, hi2;
            unpk(lo1, hi1, u1);
            unpk(lo2, hi2, u2);
            float S1 = hi ? hi1 : lo1;
            float S2 = hi ? hi2 : lo2;
            float mu = S1 * (1.f / 1024.f);
            float var = S2 * (1.f / 1024.f) - mu * mu;
            sMu[tk] = mu;
            sRs[tk] = rsqrtf(var + 1e-5f);
        }
        if (ks == 0) {
#pragma unroll
            for (int s = 1; s < 4; s++) {
                const ull* src = (const ull*)&dsm[((s - 1) * 64 + owh * 32 + oh * 8 + tg) * 16];
#pragma unroll
                for (int i = 0; i < 8; i++) ADD2(acc[i], src[i]);
            }
        }
        __syncthreads();
        if (ks == 0) {
            float mu[4], rs[4];
#pragma unroll
            for (int j = 0; j < 4; j++) { mu[j] = sMu[tg * 4 + j]; rs[j] = sRs[tg * 4 + j]; }
            int b = T0 >> 12;
            int s0 = (T0 & 4095) + tg * 4;
#pragma unroll
            for (int i = 0; i < 4; i++) {
                int o = og * 4 + i;
                float k1v = g_k1[o];
                float k2v = g_k2[o] + g_c[o];
                float v[4];
#pragma unroll
                for (int j = 0; j < 4; j++) {
                    float lo, hi;
                    unpk(lo, hi, acc[j * 2 + (i >> 1)]);
                    float val = (i & 1) ? hi : lo;
                    val = rs[j] * val - mu[j] * rs[j] * k1v + k2v;
                    if (o < 16) val = 1.f / (1.f + __expf(-val));
                    v[j] = val;
                }
                *(float4*)&g_au[(b * 32 + o) * 4096 + s0] = make_float4(v[0], v[1], v[2], v[3]);
            }
        }
    }
    gsync();

    // ================= Phase D: scan (0-31) | fold-MT (32-63) =================
    if (blk < 32) {
        __shared__ float wA[8], wU[8], pU[8];
        int bn = blk;
        int b = bn >> 4, n = bn & 15;
        const float* ap = g_au + (b * 32 + n) * 4096;
        const float* up = g_au + (b * 32 + 16 + n) * 4096;

        float a[16], u[16];
        const float4* a4 = (const float4*)(ap + tid * 16);
        const float4* u4 = (const float4*)(up + tid * 16);
#pragma unroll
        for (int q = 0; q < 4; q++) {
            float4 av = a4[q], uv = u4[q];
            a[q*4+0] = av.x; a[q*4+1] = av.y; a[q*4+2] = av.z; a[q*4+3] = av.w;
            u[q*4+0] = uv.x; u[q*4+1] = uv.y; u[q*4+2] = uv.z; u[q*4+3] = uv.w;
        }
        float Aloc = 1.f, Uloc = 0.f;
#pragma unroll
        for (int i = 0; i < 16; i++) { Uloc = Uloc * a[i] + u[i]; Aloc *= a[i]; }

        float Ai = Aloc, Ui = Uloc;
#pragma unroll
        for (int off = 1; off < 32; off <<= 1) {
            float Ap = __shfl_up_sync(0xffffffffu, Ai, off);
            float Up = __shfl_up_sync(0xffffffffu, Ui, off);
            if (lane >= off) { Ui = Up * Ai + Ui; Ai = Ap * Ai; }
        }
        if (lane == 31) { wA[wid] = Ai; wU[wid] = Ui; }
        __syncthreads();
        if (tid == 0) {
            float Uc = 0.f;
#pragma unroll
            for (int j = 0; j < 8; j++) {
                pU[j] = Uc;
                Uc = Uc * wA[j] + wU[j];
            }
        }
        __syncthreads();
        float eA = __shfl_up_sync(0xffffffffu, Ai, 1);
        float eU = __shfl_up_sync(0xffffffffu, Ui, 1);
        if (lane == 0) { eA = 1.f; eU = 0.f; }
        float s = pU[wid] * eA + eU;

        float o16[16];
#pragma unroll
        for (int i = 0; i < 16; i++) { s = a[i] * s + u[i]; o16[i] = s; }
        float4* dst = (float4*)(g_states + bn * 4096 + tid * 16);
#pragma unroll
        for (int q = 0; q < 4; q++)
            dst[q] = make_float4(o16[q*4+0], o16[q*4+1], o16[q*4+2], o16[q*4+3]);
    } else if (blk < 64) {
#pragma unroll
        for (int h = 0; h < 2; h++) {
            int base = (blk - 32) * 512 + h * 256 + tid;
            int d = base & 1023, n = base >> 10;
            float s = 0.f;
#pragma unroll
            for (int q = 0; q < 8; q++) s += g_MTp[(q * 16 + n) * 1024 + d];
            g_MT[n * 1024 + d] = s;
        }
    }
    gsync();

    // ================= Phase E: out (states pre-duplicated in smem) =================
    {
        ull* sSTd = (ull*)dsm;   // 32 tokens x 17 ull (padded)
        int T0 = blk * 32;
        int b = T0 >> 12, s0 = T0 & 4095;
#pragma unroll
        for (int it = 0; it < 2; it++) {
            int idx = tid + it * 256;
            int soff = idx & 31, n = idx >> 5;
            sSTd[soff * 17 + n] = dup_f(g_states[(b * 16 + n) * 4096 + s0 + soff]);
        }
        ull m01[16], m23[16];
#pragma unroll
        for (int n = 0; n < 16; n++) {
            ulonglong2 mm = *(const ulonglong2*)(g_MT + n * 1024 + tid * 4);
            m01[n] = mm.x; m23[n] = mm.y;
        }
        ulonglong2 bov = *(const ulonglong2*)(bo + tid * 4);
        __syncthreads();

        for (int t = 0; t < 32; t++) {
            ulonglong2 xv = *(const ulonglong2*)(x + (T0 + t) * 1024 + tid * 4);
            ull r01, r23;
            asm("add.rn.f32x2 %0, %1, %2;" : "=l"(r01) : "l"(xv.x), "l"(bov.x));
            asm("add.rn.f32x2 %0, %1, %2;" : "=l"(r23) : "l"(xv.y), "l"(bov.y));
            const ull* st = &sSTd[t * 17];
#pragma unroll
            for (int n = 0; n < 16; n++) {
                ull sv = st[n];
                FFMA2(r01, sv, m01[n]);
                FFMA2(r23, sv, m23[n]);
            }
            ulonglong2 res; res.x = r01; res.y = r23;
            *(ulonglong2*)(out + (T0 + t) * 1024 + tid * 4) = res;
        }
    }
}

// ---------------- launch ----------------
extern "C" void kernel_launch(void* const* d_in, const int* in_sizes, int n_in,
                              void* d_out, int out_size) {
    const float* x    = (const float*)d_in[0];
    const float* nw   = (const float*)d_in[1];
    const float* nb   = (const float*)d_in[2];
    const float* Win  = (const float*)d_in[3];
    const float* b_in = (const float*)d_in[4];
    const float* A    = (const float*)d_in[5];
    const float* Bs   = (const float*)d_in[6];
    const float* C    = (const float*)d_in[7];
    const float* Wout = (const float*)d_in[8];
    const float* bo   = (const float*)d_in[9];
    float* out = (float*)d_out;

    cudaFuncSetAttribute(k_main, cudaFuncAttributeMaxDynamicSharedMemorySize, 34816);

    k_main<<<GRID, NT, 34816>>>(x, nw, nb, Win, b_in, A, Bs, C, Wout, bo, out);
}